// round 2
// baseline (speedup 1.0000x reference)
#include <cuda_runtime.h>
#include <cuda_bf16.h>

// Problem constants (from reference setup_inputs)
#define B_  16
#define M_  512
#define S_  32
#define E_  128

// Scratch (allocation-free): memory[B,M,E], output[B,M,E], x[B,E]
__device__ float g_memory[B_ * M_ * E_];
__device__ float g_output[B_ * M_ * E_];
__device__ float g_x[B_ * E_];

// enc[s][e] = 1 + (e+1 - E/2)*(s+1 - S/2) * 4/(E*S) = 1 + (e-63)*(s-15)/1024

// ---------------------------------------------------------------------------
// Kernel 1: story embeddings -> memory[b,m,:] (+bias) and output[b,m,:]
// grid (M, B), block 128. 4 warps each handle 8 sentences; float4 row gathers.
// ---------------------------------------------------------------------------
__global__ void __launch_bounds__(128) embed_kernel(
    const int* __restrict__ stories,
    const float* __restrict__ stab,   // stories_biases [Vm1, E]
    const float* __restrict__ otab,   // output_biases  [Vm1, E]
    const float* __restrict__ mbias,  // memory_biases  [M, E]
    int Vm1)
{
    const int m = blockIdx.x;
    const int b = blockIdx.y;
    const int tid = threadIdx.x;

    __shared__ int sidx[S_];
    __shared__ float red[2][4][E_];   // [mem/out][group][e]

    if (tid < S_) sidx[tid] = stories[(b * M_ + m) * S_ + tid];
    __syncthreads();

    const int lane = tid & 31;
    const int grp  = tid >> 5;

    const float4* __restrict__ stab4 = reinterpret_cast<const float4*>(stab);
    const float4* __restrict__ otab4 = reinterpret_cast<const float4*>(otab);

    float am0 = 0.f, am1 = 0.f, am2 = 0.f, am3 = 0.f;
    float ao0 = 0.f, ao1 = 0.f, ao2 = 0.f, ao3 = 0.f;
    const float ef0 = (float)(lane * 4 - 63);  // e+1-64 for k=0

    #pragma unroll
    for (int it = 0; it < 8; ++it) {
        const int s = grp + it * 4;
        const int idx = sidx[s];
        float4 av = make_float4(0.f, 0.f, 0.f, 0.f);
        float4 ov = make_float4(0.f, 0.f, 0.f, 0.f);
        if (idx < Vm1) {
            const size_t ro = (size_t)idx * (E_ / 4) + lane;
            av = stab4[ro];
            ov = otab4[ro];
        }
        const float sf = (float)(s - 15) * (1.0f / 1024.0f);
        const float e0 = 1.f + ef0 * sf;
        const float e1 = 1.f + (ef0 + 1.f) * sf;
        const float e2 = 1.f + (ef0 + 2.f) * sf;
        const float e3 = 1.f + (ef0 + 3.f) * sf;
        am0 += e0 * av.x; am1 += e1 * av.y; am2 += e2 * av.z; am3 += e3 * av.w;
        ao0 += e0 * ov.x; ao1 += e1 * ov.y; ao2 += e2 * ov.z; ao3 += e3 * ov.w;
    }

    // store partials (16B-aligned)
    *reinterpret_cast<float4*>(&red[0][grp][lane * 4]) = make_float4(am0, am1, am2, am3);
    *reinterpret_cast<float4*>(&red[1][grp][lane * 4]) = make_float4(ao0, ao1, ao2, ao3);
    __syncthreads();

    // thread tid owns e = tid: sum across the 4 groups
    const float mv = red[0][0][tid] + red[0][1][tid] + red[0][2][tid] + red[0][3][tid]
                   + mbias[m * E_ + tid];
    const float ov2 = red[1][0][tid] + red[1][1][tid] + red[1][2][tid] + red[1][3][tid];

    const size_t o = ((size_t)(b * M_ + m)) * E_ + tid;
    g_memory[o] = mv;
    g_output[o] = ov2;
}

// ---------------------------------------------------------------------------
// Kernel 2: query embedding + 3 hops. grid B, block 256. Everything in smem.
// ---------------------------------------------------------------------------
__global__ void __launch_bounds__(256) hops_kernel(
    const int* __restrict__ queries,
    const float* __restrict__ qtab,     // query_biases [Vm1, E]
    const float* __restrict__ w_inter,  // [E, E]
    const float* __restrict__ w_out,    // [E, E]
    int Vm1)
{
    const int b = blockIdx.x;
    const int tid = threadIdx.x;
    const int lane = tid & 31;
    const int wid = tid >> 5;

    __shared__ float q[E_];
    __shared__ float sc[M_];
    __shared__ float xs[E_];
    __shared__ float redL[256];
    __shared__ float wred[8];
    __shared__ float s_bcast;
    __shared__ int qidx[S_];

    if (tid < S_) qidx[tid] = queries[b * S_ + tid];
    __syncthreads();

    // query embedding: q[e] = sum_s enc[s][e] * qtab[idx_s][e]
    if (tid < E_) {
        float acc = 0.f;
        const float ef = (float)(tid - 63);
        #pragma unroll
        for (int s = 0; s < S_; ++s) {
            const int idx = qidx[s];
            const float v = (idx < Vm1) ? qtab[(size_t)idx * E_ + tid] : 0.f;
            const float enc = 1.f + ef * (float)(s - 15) * (1.0f / 1024.0f);
            acc += enc * v;
        }
        q[tid] = acc;
    }
    __syncthreads();

    for (int hop = 0; hop < 3; ++hop) {
        // --- scores: sc[m] = memory[b,m,:] . q ---
        const float4 qv = reinterpret_cast<const float4*>(q)[lane];
        const float4* __restrict__ mem4 =
            reinterpret_cast<const float4*>(g_memory) + (size_t)b * M_ * (E_ / 4);
        for (int m = wid; m < M_; m += 8) {
            const float4 v = mem4[m * (E_ / 4) + lane];
            float d = v.x * qv.x + v.y * qv.y + v.z * qv.z + v.w * qv.w;
            #pragma unroll
            for (int off = 16; off; off >>= 1)
                d += __shfl_xor_sync(0xffffffffu, d, off);
            if (lane == 0) sc[m] = d;
        }
        __syncthreads();

        // --- softmax over 512 ---
        float lm = fmaxf(sc[tid], sc[tid + 256]);
        #pragma unroll
        for (int off = 16; off; off >>= 1)
            lm = fmaxf(lm, __shfl_xor_sync(0xffffffffu, lm, off));
        if (lane == 0) wred[wid] = lm;
        __syncthreads();
        if (tid == 0) {
            float mx = wred[0];
            #pragma unroll
            for (int i = 1; i < 8; ++i) mx = fmaxf(mx, wred[i]);
            s_bcast = mx;
        }
        __syncthreads();
        const float mx = s_bcast;
        const float p0 = expf(sc[tid] - mx);
        const float p1 = expf(sc[tid + 256] - mx);
        sc[tid] = p0;
        sc[tid + 256] = p1;
        float ls = p0 + p1;
        #pragma unroll
        for (int off = 16; off; off >>= 1)
            ls += __shfl_xor_sync(0xffffffffu, ls, off);
        if (lane == 0) wred[wid] = ls;
        __syncthreads();
        if (tid == 0) {
            float sm = 0.f;
            #pragma unroll
            for (int i = 0; i < 8; ++i) sm += wred[i];
            s_bcast = 1.0f / sm;
        }
        __syncthreads();
        const float inv = s_bcast;
        sc[tid] *= inv;
        sc[tid + 256] *= inv;
        __syncthreads();

        // --- layer_out[e] = sum_m probs[m] * output[b,m,e], split m over 2 halves ---
        {
            const int half = tid >> 7;
            const int e = tid & 127;
            const float* __restrict__ op =
                g_output + ((size_t)b * M_ + half * 256) * E_ + e;
            float acc = 0.f;
            #pragma unroll 8
            for (int m = 0; m < 256; ++m)
                acc += sc[half * 256 + m] * op[(size_t)m * E_];
            redL[tid] = acc;
        }
        __syncthreads();

        if (tid < E_)
            xs[tid] = q[tid] + redL[tid] + redL[tid + 128];
        __syncthreads();

        // --- (q + layer) @ W ---
        float newq = 0.f;
        if (tid < E_) {
            const float* __restrict__ W = (hop == 2) ? w_out : w_inter;
            float a = 0.f;
            #pragma unroll 8
            for (int e2 = 0; e2 < E_; ++e2)
                a += xs[e2] * W[e2 * E_ + tid];
            newq = a;
        }
        __syncthreads();
        if (tid < E_) q[tid] = newq;
        __syncthreads();
    }

    if (tid < E_) g_x[b * E_ + tid] = fmaxf(q[tid], 0.f);
}

// ---------------------------------------------------------------------------
// Kernel 3: out[b,v] = relu_x[b,:] @ w_final[:,v].  x transposed in smem so
// per-e reads are LDS.128 broadcasts. block 128 threads = 128 vocab columns.
// ---------------------------------------------------------------------------
__global__ void __launch_bounds__(128) final_kernel(
    const float* __restrict__ wf,   // [E, V]
    float* __restrict__ out,        // [B, V]
    int V)
{
    __shared__ float xs[E_ * B_];   // xs[e*16 + b]
    const int tid = threadIdx.x;
    for (int i = tid; i < B_ * E_; i += 128) {
        const int b = i >> 7;
        const int e = i & 127;
        xs[e * B_ + b] = g_x[i];
    }
    __syncthreads();

    const int v = blockIdx.x * 128 + tid;
    if (v >= V) return;

    float acc[B_];
    #pragma unroll
    for (int b = 0; b < B_; ++b) acc[b] = 0.f;

    #pragma unroll 4
    for (int e = 0; e < E_; ++e) {
        const float w = wf[(size_t)e * V + v];
        const float4* xv4 = reinterpret_cast<const float4*>(xs + e * B_);
        #pragma unroll
        for (int b4 = 0; b4 < 4; ++b4) {
            const float4 xv = xv4[b4];
            acc[b4 * 4 + 0] += xv.x * w;
            acc[b4 * 4 + 1] += xv.y * w;
            acc[b4 * 4 + 2] += xv.z * w;
            acc[b4 * 4 + 3] += xv.w * w;
        }
    }

    #pragma unroll
    for (int b = 0; b < B_; ++b)
        out[(size_t)b * V + v] = acc[b];
}

// ---------------------------------------------------------------------------
extern "C" void kernel_launch(void* const* d_in, const int* in_sizes, int n_in,
                              void* d_out, int out_size)
{
    const int*   queries = (const int*)d_in[0];
    const int*   stories = (const int*)d_in[1];
    const float* qb      = (const float*)d_in[2];
    const float* sb      = (const float*)d_in[3];
    const float* mb      = (const float*)d_in[4];
    const float* ob      = (const float*)d_in[5];
    const float* wi      = (const float*)d_in[6];
    const float* wo      = (const float*)d_in[7];
    const float* wf      = (const float*)d_in[8];

    const int Vm1 = in_sizes[2] / E_;       // rows in bias tables (nil index == Vm1)
    const int V   = out_size / B_;          // vocab size

    embed_kernel<<<dim3(M_, B_), 128>>>(stories, sb, ob, mb, Vm1);
    hops_kernel<<<B_, 256>>>(queries, qb, wi, wo, Vm1);
    final_kernel<<<(V + 127) / 128, 128>>>(wf, (float*)d_out, V);
}

// round 3
// speedup vs baseline: 1.9932x; 1.9932x over previous
#include <cuda_runtime.h>
#include <cuda_bf16.h>

#define B_  16
#define M_  512
#define S_  32
#define E_  128

// Scratch (allocation-free)
__device__ float g_memory[B_ * M_ * E_];
__device__ float g_output[B_ * M_ * E_];
__device__ float g_q[B_ * E_];
__device__ float g_scores[B_ * M_];
__device__ float g_x[B_ * E_];

// enc[s][e] = 1 + (e-63)*(s-15)/1024

// ---------------------------------------------------------------------------
// Kernel 1: story embeddings -> memory[b,m,:] (+bias) and output[b,m,:]
// grid (M, B), block 128. At the LTS roofline (~23.6us) — traffic-bound.
// ---------------------------------------------------------------------------
__global__ void __launch_bounds__(128) embed_kernel(
    const int* __restrict__ stories,
    const float* __restrict__ stab,
    const float* __restrict__ otab,
    const float* __restrict__ mbias,
    int Vm1)
{
    const int m = blockIdx.x;
    const int b = blockIdx.y;
    const int tid = threadIdx.x;

    __shared__ int sidx[S_];
    __shared__ float red[2][4][E_];

    if (tid < S_) sidx[tid] = stories[(b * M_ + m) * S_ + tid];
    __syncthreads();

    const int lane = tid & 31;
    const int grp  = tid >> 5;

    const float4* __restrict__ stab4 = reinterpret_cast<const float4*>(stab);
    const float4* __restrict__ otab4 = reinterpret_cast<const float4*>(otab);

    float am0 = 0.f, am1 = 0.f, am2 = 0.f, am3 = 0.f;
    float ao0 = 0.f, ao1 = 0.f, ao2 = 0.f, ao3 = 0.f;
    const float ef0 = (float)(lane * 4 - 63);

    #pragma unroll
    for (int it = 0; it < 8; ++it) {
        const int s = grp + it * 4;
        const int idx = sidx[s];
        float4 av = make_float4(0.f, 0.f, 0.f, 0.f);
        float4 ov = make_float4(0.f, 0.f, 0.f, 0.f);
        if (idx < Vm1) {
            const size_t ro = (size_t)idx * (E_ / 4) + lane;
            av = stab4[ro];
            ov = otab4[ro];
        }
        const float sf = (float)(s - 15) * (1.0f / 1024.0f);
        const float e0 = 1.f + ef0 * sf;
        const float e1 = 1.f + (ef0 + 1.f) * sf;
        const float e2 = 1.f + (ef0 + 2.f) * sf;
        const float e3 = 1.f + (ef0 + 3.f) * sf;
        am0 += e0 * av.x; am1 += e1 * av.y; am2 += e2 * av.z; am3 += e3 * av.w;
        ao0 += e0 * ov.x; ao1 += e1 * ov.y; ao2 += e2 * ov.z; ao3 += e3 * ov.w;
    }

    *reinterpret_cast<float4*>(&red[0][grp][lane * 4]) = make_float4(am0, am1, am2, am3);
    *reinterpret_cast<float4*>(&red[1][grp][lane * 4]) = make_float4(ao0, ao1, ao2, ao3);
    __syncthreads();

    const float mv = red[0][0][tid] + red[0][1][tid] + red[0][2][tid] + red[0][3][tid]
                   + mbias[m * E_ + tid];
    const float ov2 = red[1][0][tid] + red[1][1][tid] + red[1][2][tid] + red[1][3][tid];

    const size_t o = ((size_t)(b * M_ + m)) * E_ + tid;
    g_memory[o] = mv;
    g_output[o] = ov2;
}

// ---------------------------------------------------------------------------
// Kernel 2: query embedding. grid B, block 128.
// ---------------------------------------------------------------------------
__global__ void __launch_bounds__(128) query_kernel(
    const int* __restrict__ queries,
    const float* __restrict__ qtab,
    int Vm1)
{
    const int b = blockIdx.x;
    const int tid = threadIdx.x;

    __shared__ int qidx[S_];
    if (tid < S_) qidx[tid] = queries[b * S_ + tid];
    __syncthreads();

    float acc = 0.f;
    const float ef = (float)(tid - 63);
    #pragma unroll
    for (int s = 0; s < S_; ++s) {
        const int idx = qidx[s];
        const float v = (idx < Vm1) ? qtab[(size_t)idx * E_ + tid] : 0.f;
        const float enc = 1.f + ef * (float)(s - 15) * (1.0f / 1024.0f);
        acc += enc * v;
    }
    g_q[b * E_ + tid] = acc;
}

// ---------------------------------------------------------------------------
// Kernel 3 (per hop): scores[b,m] = memory[b,m,:] . q[b,:]
// grid (4, B), block 128 = 4 warps x 32 m each. Shuffle-free smem reduce.
// ---------------------------------------------------------------------------
__global__ void __launch_bounds__(128) score_kernel()
{
    const int b = blockIdx.y;
    const int mbase = blockIdx.x * 128;
    const int tid = threadIdx.x;
    const int lane = tid & 31;
    const int w = tid >> 5;

    __shared__ float part[4][32][33];

    const float* __restrict__ q = g_q + b * E_;
    const float q0 = q[lane];
    const float q1 = q[lane + 32];
    const float q2 = q[lane + 64];
    const float q3 = q[lane + 96];

    const float* __restrict__ mem =
        g_memory + ((size_t)b * M_ + mbase + w * 32) * E_;

    #pragma unroll
    for (int i = 0; i < 32; ++i) {
        const float* __restrict__ r = mem + i * E_;
        part[w][i][lane] = r[lane] * q0 + r[lane + 32] * q1
                         + r[lane + 64] * q2 + r[lane + 96] * q3;
    }
    __syncwarp();

    float s = 0.f;
    #pragma unroll
    for (int l = 0; l < 32; ++l) s += part[w][lane][l];
    g_scores[b * M_ + mbase + w * 32 + lane] = s;
}

// ---------------------------------------------------------------------------
// Kernel 4 (per hop): softmax + layer_out + (q+layer)@W.  grid B, block 512.
// ---------------------------------------------------------------------------
__global__ void __launch_bounds__(512) update_kernel(
    const float* __restrict__ W, int last)
{
    const int b = blockIdx.x;
    const int tid = threadIdx.x;
    const int lane = tid & 31;
    const int wid = tid >> 5;

    __shared__ float sc[M_];
    __shared__ float red[512];
    __shared__ float wred[16];
    __shared__ float q[E_];
    __shared__ float xs[E_];
    __shared__ float bc;

    const float v = g_scores[b * M_ + tid];
    sc[tid] = v;
    if (tid < E_) q[tid] = g_q[b * E_ + tid];

    // --- softmax: max ---
    float lm = v;
    #pragma unroll
    for (int off = 16; off; off >>= 1)
        lm = fmaxf(lm, __shfl_xor_sync(0xffffffffu, lm, off));
    if (lane == 0) wred[wid] = lm;
    __syncthreads();
    if (tid == 0) {
        float mx = wred[0];
        #pragma unroll
        for (int i = 1; i < 16; ++i) mx = fmaxf(mx, wred[i]);
        bc = mx;
    }
    __syncthreads();

    // --- exp + sum ---
    float p = __expf(v - bc);
    float ls = p;
    #pragma unroll
    for (int off = 16; off; off >>= 1)
        ls += __shfl_xor_sync(0xffffffffu, ls, off);
    if (lane == 0) wred[wid] = ls;
    __syncthreads();
    if (tid == 0) {
        float sm = 0.f;
        #pragma unroll
        for (int i = 0; i < 16; ++i) sm += wred[i];
        bc = 1.0f / sm;
    }
    __syncthreads();
    sc[tid] = p * bc;
    __syncthreads();

    // --- layer_out[e] = sum_m probs[m]*output[b,m,e], m split 4 ways ---
    const int e = tid & 127;
    const int qt = tid >> 7;
    {
        const float* __restrict__ op =
            g_output + ((size_t)b * M_ + qt * 128) * E_ + e;
        const float* __restrict__ pp = &sc[qt * 128];
        float acc = 0.f;
        #pragma unroll 16
        for (int m = 0; m < 128; ++m)
            acc += pp[m] * op[(size_t)m * E_];
        red[tid] = acc;
    }
    __syncthreads();
    if (tid < E_)
        xs[tid] = q[tid] + red[tid] + red[tid + 128] + red[tid + 256] + red[tid + 384];
    __syncthreads();

    // --- newq[e] = sum_e2 xs[e2] * W[e2,e], e2 split 4 ways ---
    {
        const float* __restrict__ Wc = W + qt * 32 * E_ + e;
        const float* __restrict__ xp = &xs[qt * 32];
        float a = 0.f;
        #pragma unroll
        for (int k = 0; k < 32; ++k)
            a += xp[k] * Wc[(size_t)k * E_];
        red[tid] = a;
    }
    __syncthreads();
    if (tid < E_) {
        const float nq = red[tid] + red[tid + 128] + red[tid + 256] + red[tid + 384];
        if (last) g_x[b * E_ + tid] = fmaxf(nq, 0.f);
        else      g_q[b * E_ + tid] = nq;
    }
}

// ---------------------------------------------------------------------------
// Kernel 5: out[b,v] = relu_x[b,:] @ w_final[:,v]. unroll 16 for MLP.
// ---------------------------------------------------------------------------
__global__ void __launch_bounds__(128) final_kernel(
    const float* __restrict__ wf,
    float* __restrict__ out,
    int V)
{
    __shared__ float xsm[E_ * B_];   // xsm[e*16 + b]
    const int tid = threadIdx.x;
    for (int i = tid; i < B_ * E_; i += 128) {
        const int b = i >> 7;
        const int e = i & 127;
        xsm[e * B_ + b] = g_x[i];
    }
    __syncthreads();

    const int v = blockIdx.x * 128 + tid;
    if (v >= V) return;

    float acc[B_];
    #pragma unroll
    for (int b = 0; b < B_; ++b) acc[b] = 0.f;

    #pragma unroll 16
    for (int e = 0; e < E_; ++e) {
        const float w = wf[(size_t)e * V + v];
        const float4* xv4 = reinterpret_cast<const float4*>(xsm + e * B_);
        #pragma unroll
        for (int b4 = 0; b4 < 4; ++b4) {
            const float4 xv = xv4[b4];
            acc[b4 * 4 + 0] += xv.x * w;
            acc[b4 * 4 + 1] += xv.y * w;
            acc[b4 * 4 + 2] += xv.z * w;
            acc[b4 * 4 + 3] += xv.w * w;
        }
    }

    #pragma unroll
    for (int b = 0; b < B_; ++b)
        out[(size_t)b * V + v] = acc[b];
}

// ---------------------------------------------------------------------------
extern "C" void kernel_launch(void* const* d_in, const int* in_sizes, int n_in,
                              void* d_out, int out_size)
{
    const int*   queries = (const int*)d_in[0];
    const int*   stories = (const int*)d_in[1];
    const float* qb      = (const float*)d_in[2];
    const float* sb      = (const float*)d_in[3];
    const float* mb      = (const float*)d_in[4];
    const float* ob      = (const float*)d_in[5];
    const float* wi      = (const float*)d_in[6];
    const float* wo      = (const float*)d_in[7];
    const float* wf      = (const float*)d_in[8];

    const int Vm1 = in_sizes[2] / E_;
    const int V   = out_size / B_;

    embed_kernel<<<dim3(M_, B_), 128>>>(stories, sb, ob, mb, Vm1);
    query_kernel<<<B_, 128>>>(queries, qb, Vm1);

    for (int hop = 0; hop < 3; ++hop) {
        score_kernel<<<dim3(4, B_), 128>>>();
        update_kernel<<<B_, 512>>>(hop == 2 ? wo : wi, hop == 2 ? 1 : 0);
    }

    final_kernel<<<(V + 127) / 128, 128>>>(wf, (float*)d_out, V);
}